// round 1
// baseline (speedup 1.0000x reference)
#include <cuda_runtime.h>
#include <math.h>

#define NTOK 2048
#define DIM_ 2048
#define HID_ 7168
#define NEXP 8

#define BM 64
#define BN 64
#define BK 16
#define SA (BK + 4)   // A smem stride 20 -> conflict-free frag loads
#define SB (BN + 8)   // B smem stride 72 -> conflict-free frag loads

// ---------------- device scratch (no dynamic alloc allowed) ----------------
__device__ int   g_cnt[NEXP];
__device__ int   g_tok[NEXP * NTOK];
__device__ float g_wt [NEXP * NTOK];
__device__ float g_act[(size_t)NTOK * 2 * HID_];   // 4096 x 7168 fp32 = 117MB

// ---------------- helpers ----------------
__device__ __forceinline__ float to_tf32(float f) {
    unsigned u;
    asm("cvt.rna.tf32.f32 %0, %1;" : "=r"(u) : "f"(f));
    return __uint_as_float(u);
}

__device__ __forceinline__ void mma8(float* c, const float* a, const float* b) {
    asm volatile(
        "mma.sync.aligned.m16n8k8.row.col.f32.tf32.tf32.f32 "
        "{%0,%1,%2,%3}, {%4,%5,%6,%7}, {%8,%9}, {%0,%1,%2,%3};\n"
        : "+f"(c[0]), "+f"(c[1]), "+f"(c[2]), "+f"(c[3])
        : "r"(__float_as_uint(a[0])), "r"(__float_as_uint(a[1])),
          "r"(__float_as_uint(a[2])), "r"(__float_as_uint(a[3])),
          "r"(__float_as_uint(b[0])), "r"(__float_as_uint(b[1])));
}

__global__ void zero_cnt_kernel() {
    if (threadIdx.x < NEXP) g_cnt[threadIdx.x] = 0;
}

// ---------------- gating: scores, top-2, softmax, routing lists ----------------
__global__ __launch_bounds__(128) void gate_kernel(const float* __restrict__ x,
                                                   const float* __restrict__ Wg) {
    __shared__ float red[128 * NEXP];
    __shared__ float sc[NEXP];
    int t = blockIdx.x;
    const float* xr = x + (size_t)t * DIM_;
    float acc[NEXP];
#pragma unroll
    for (int e = 0; e < NEXP; e++) acc[e] = 0.f;
    for (int i = threadIdx.x; i < DIM_; i += 128) {
        float xv = xr[i];
        const float4* w4 = reinterpret_cast<const float4*>(Wg + (size_t)i * NEXP);
        float4 wa = w4[0], wb = w4[1];
        acc[0] += xv * wa.x; acc[1] += xv * wa.y;
        acc[2] += xv * wa.z; acc[3] += xv * wa.w;
        acc[4] += xv * wb.x; acc[5] += xv * wb.y;
        acc[6] += xv * wb.z; acc[7] += xv * wb.w;
    }
#pragma unroll
    for (int e = 0; e < NEXP; e++) red[threadIdx.x * NEXP + e] = acc[e];
    __syncthreads();
    if (threadIdx.x < NEXP) {
        int e = threadIdx.x;
        float s = 0.f;
        for (int i = 0; i < 128; i++) s += red[i * NEXP + e];
        sc[e] = s;
    }
    __syncthreads();
    if (threadIdx.x == 0) {
        int i1 = 0;
#pragma unroll
        for (int e = 1; e < NEXP; e++) if (sc[e] > sc[i1]) i1 = e;
        int i2 = (i1 == 0) ? 1 : 0;
#pragma unroll
        for (int e = 0; e < NEXP; e++) if (e != i1 && sc[e] > sc[i2]) i2 = e;
        float e2 = expf(sc[i2] - sc[i1]);
        float wa = 1.f / (1.f + e2);
        float wb = e2 / (1.f + e2);
        int s1 = atomicAdd(&g_cnt[i1], 1);
        g_tok[i1 * NTOK + s1] = t; g_wt[i1 * NTOK + s1] = wa;
        int s2 = atomicAdd(&g_cnt[i2], 1);
        g_tok[i2 * NTOK + s2] = t; g_wt[i2 * NTOK + s2] = wb;
    }
}

// ---------------- FFN1: gathered X @ {w1,w3} + SwiGLU -> g_act ----------------
// grid: (NTOK/BM [m fastest for L2 weight reuse], HID/BN, NEXP)
__global__ __launch_bounds__(256) void ffn1_kernel(const float* __restrict__ x,
                                                   const float* __restrict__ w1,
                                                   const float* __restrict__ w3) {
    int e = blockIdx.z;
    int cnt = g_cnt[e];
    int m0 = blockIdx.x * BM;
    if (m0 >= cnt) return;
    int n0 = blockIdx.y * BN;
    int base = 0;
#pragma unroll
    for (int i = 0; i < NEXP; i++) base += (i < e) ? g_cnt[i] : 0;

    const float* W1 = w1 + (size_t)e * DIM_ * HID_;
    const float* W3 = w3 + (size_t)e * DIM_ * HID_;

    __shared__ float As[BM][SA];
    __shared__ float B1s[BK][SB];
    __shared__ float B3s[BK][SB];
    __shared__ int   toks[BM];

    int tid = threadIdx.x;
    if (tid < BM) {
        int m = m0 + tid;
        toks[tid] = (m < cnt) ? g_tok[e * NTOK + m] : -1;
    }
    __syncthreads();

    int lane = tid & 31, warp = tid >> 5;
    int wm = (warp >> 2) << 5;   // 0 / 32
    int wn = (warp & 3) << 4;    // 0,16,32,48
    int r = lane >> 2, q = lane & 3;

    int ar = tid >> 2, ac = (tid & 3) << 2;   // A: 64 rows x 16 cols
    int br = tid >> 4, bc = (tid & 15) << 2;  // B: 16 rows x 64 cols
    int my_tok = toks[ar];
    const float* xrow = x + (size_t)(my_tok >= 0 ? my_tok : 0) * DIM_;

    float c1[2][2][4], c3[2][2][4];
#pragma unroll
    for (int i = 0; i < 2; i++)
#pragma unroll
        for (int j = 0; j < 2; j++)
#pragma unroll
            for (int k = 0; k < 4; k++) { c1[i][j][k] = 0.f; c3[i][j][k] = 0.f; }

    for (int k0 = 0; k0 < DIM_; k0 += BK) {
        float4 av = make_float4(0.f, 0.f, 0.f, 0.f);
        if (my_tok >= 0) av = *reinterpret_cast<const float4*>(xrow + k0 + ac);
        As[ar][ac + 0] = to_tf32(av.x);
        As[ar][ac + 1] = to_tf32(av.y);
        As[ar][ac + 2] = to_tf32(av.z);
        As[ar][ac + 3] = to_tf32(av.w);
        size_t boff = (size_t)(k0 + br) * HID_ + n0 + bc;
        float4 b1 = *reinterpret_cast<const float4*>(W1 + boff);
        float4 b3 = *reinterpret_cast<const float4*>(W3 + boff);
        B1s[br][bc + 0] = to_tf32(b1.x); B1s[br][bc + 1] = to_tf32(b1.y);
        B1s[br][bc + 2] = to_tf32(b1.z); B1s[br][bc + 3] = to_tf32(b1.w);
        B3s[br][bc + 0] = to_tf32(b3.x); B3s[br][bc + 1] = to_tf32(b3.y);
        B3s[br][bc + 2] = to_tf32(b3.z); B3s[br][bc + 3] = to_tf32(b3.w);
        __syncthreads();
#pragma unroll
        for (int ks = 0; ks < BK; ks += 8) {
            float a[2][4];
#pragma unroll
            for (int mi = 0; mi < 2; mi++) {
                int rb = wm + (mi << 4) + r;
                a[mi][0] = As[rb][ks + q];
                a[mi][1] = As[rb + 8][ks + q];
                a[mi][2] = As[rb][ks + q + 4];
                a[mi][3] = As[rb + 8][ks + q + 4];
            }
#pragma unroll
            for (int ni = 0; ni < 2; ni++) {
                int nb = wn + (ni << 3) + r;
                float b1f[2] = { B1s[ks + q][nb], B1s[ks + q + 4][nb] };
                float b3f[2] = { B3s[ks + q][nb], B3s[ks + q + 4][nb] };
#pragma unroll
                for (int mi = 0; mi < 2; mi++) {
                    mma8(c1[mi][ni], a[mi], b1f);
                    mma8(c3[mi][ni], a[mi], b3f);
                }
            }
        }
        __syncthreads();
    }
    // epilogue: SwiGLU -> activation scratch
#pragma unroll
    for (int mi = 0; mi < 2; mi++) {
#pragma unroll
        for (int rr = 0; rr < 2; rr++) {
            int m = m0 + wm + (mi << 4) + r + (rr << 3);
            if (m < cnt) {
                size_t rowoff = (size_t)(base + m) * HID_;
#pragma unroll
                for (int ni = 0; ni < 2; ni++) {
                    int col = n0 + wn + (ni << 3) + (q << 1);
#pragma unroll
                    for (int cc = 0; cc < 2; cc++) {
                        float u = c1[mi][ni][(rr << 1) + cc];
                        float v = c3[mi][ni][(rr << 1) + cc];
                        float h = (u / (1.f + expf(-u))) * v;
                        g_act[rowoff + col + cc] = h;
                    }
                }
            }
        }
    }
}

// ---------------- FFN2: g_act @ w2, weighted scatter-add into out ----------------
// grid: (NTOK/BM, DIM/BN, NEXP)
__global__ __launch_bounds__(256) void ffn2_kernel(const float* __restrict__ w2,
                                                   float* __restrict__ out) {
    int e = blockIdx.z;
    int cnt = g_cnt[e];
    int m0 = blockIdx.x * BM;
    if (m0 >= cnt) return;
    int n0 = blockIdx.y * BN;
    int base = 0;
#pragma unroll
    for (int i = 0; i < NEXP; i++) base += (i < e) ? g_cnt[i] : 0;
    const float* W2 = w2 + (size_t)e * HID_ * DIM_;

    __shared__ float As[BM][SA];
    __shared__ float Bs[BK][SB];

    int tid = threadIdx.x;
    int lane = tid & 31, warp = tid >> 5;
    int wm = (warp >> 2) << 5;
    int wn = (warp & 3) << 4;
    int r = lane >> 2, q = lane & 3;
    int ar = tid >> 2, ac = (tid & 3) << 2;
    int br = tid >> 4, bc = (tid & 15) << 2;

    bool avalid = (m0 + ar) < cnt;
    const float* arow = g_act + (size_t)(base + m0 + (avalid ? ar : 0)) * HID_;

    float c[2][2][4];
#pragma unroll
    for (int i = 0; i < 2; i++)
#pragma unroll
        for (int j = 0; j < 2; j++)
#pragma unroll
            for (int k = 0; k < 4; k++) c[i][j][k] = 0.f;

    for (int k0 = 0; k0 < HID_; k0 += BK) {
        float4 av = make_float4(0.f, 0.f, 0.f, 0.f);
        if (avalid) av = *reinterpret_cast<const float4*>(arow + k0 + ac);
        As[ar][ac + 0] = to_tf32(av.x);
        As[ar][ac + 1] = to_tf32(av.y);
        As[ar][ac + 2] = to_tf32(av.z);
        As[ar][ac + 3] = to_tf32(av.w);
        float4 bv = *reinterpret_cast<const float4*>(W2 + (size_t)(k0 + br) * DIM_ + n0 + bc);
        Bs[br][bc + 0] = to_tf32(bv.x); Bs[br][bc + 1] = to_tf32(bv.y);
        Bs[br][bc + 2] = to_tf32(bv.z); Bs[br][bc + 3] = to_tf32(bv.w);
        __syncthreads();
#pragma unroll
        for (int ks = 0; ks < BK; ks += 8) {
            float a[2][4];
#pragma unroll
            for (int mi = 0; mi < 2; mi++) {
                int rb = wm + (mi << 4) + r;
                a[mi][0] = As[rb][ks + q];
                a[mi][1] = As[rb + 8][ks + q];
                a[mi][2] = As[rb][ks + q + 4];
                a[mi][3] = As[rb + 8][ks + q + 4];
            }
#pragma unroll
            for (int ni = 0; ni < 2; ni++) {
                int nb = wn + (ni << 3) + r;
                float bf[2] = { Bs[ks + q][nb], Bs[ks + q + 4][nb] };
#pragma unroll
                for (int mi = 0; mi < 2; mi++) {
                    mma8(c[mi][ni], a[mi], bf);
                }
            }
        }
        __syncthreads();
    }
    // epilogue: weighted scatter-add
#pragma unroll
    for (int mi = 0; mi < 2; mi++) {
#pragma unroll
        for (int rr = 0; rr < 2; rr++) {
            int m = m0 + wm + (mi << 4) + r + (rr << 3);
            if (m < cnt) {
                int t = g_tok[e * NTOK + m];
                float wgt = g_wt[e * NTOK + m];
                float* orow = out + (size_t)t * DIM_;
#pragma unroll
                for (int ni = 0; ni < 2; ni++) {
                    int col = n0 + wn + (ni << 3) + (q << 1);
                    atomicAdd(&orow[col],     wgt * c[mi][ni][(rr << 1)]);
                    atomicAdd(&orow[col + 1], wgt * c[mi][ni][(rr << 1) + 1]);
                }
            }
        }
    }
}

// ---------------- launch ----------------
extern "C" void kernel_launch(void* const* d_in, const int* in_sizes, int n_in,
                              void* d_out, int out_size) {
    const float* x  = (const float*)d_in[0];
    const float* Wg = (const float*)d_in[1];
    const float* w1 = (const float*)d_in[2];
    const float* w3 = (const float*)d_in[3];
    const float* w2 = (const float*)d_in[4];
    float* out = (float*)d_out;

    cudaMemsetAsync(out, 0, (size_t)out_size * sizeof(float), 0);
    zero_cnt_kernel<<<1, 32>>>();
    gate_kernel<<<NTOK, 128>>>(x, Wg);
    dim3 g1(NTOK / BM, HID_ / BN, NEXP);   // m fastest -> weight L2 reuse
    ffn1_kernel<<<g1, 256>>>(x, w1, w3);
    dim3 g2(NTOK / BM, DIM_ / BN, NEXP);
    ffn2_kernel<<<g2, 256>>>(w2, out);
}

// round 3
// speedup vs baseline: 1.1916x; 1.1916x over previous
#include <cuda_runtime.h>
#include <math.h>

#define NTOK 2048
#define DIM_ 2048
#define HID_ 7168
#define NEXP 8

#define BM  128
#define BK  16
#define BN1 64      // ffn1 N tile (doubled over w1/w3)
#define BN2 128     // ffn2 N tile
#define SA  20      // A smem stride: 20r+q covers all banks
#define SB1 72      // 72 mod 32 = 8 -> q*8+r conflict-free
#define SB2 136     // 136 mod 32 = 8 -> conflict-free

// ---------------- device scratch ----------------
__device__ int   g_cnt[NEXP];
__device__ int   g_tok[NEXP * NTOK];
__device__ float g_wt [NEXP * NTOK];
__device__ float g_act[(size_t)NTOK * 2 * HID_];   // 4096 x 7168 fp32

// ---------------- helpers ----------------
__device__ __forceinline__ float to_tf32(float f) {
    unsigned u;
    asm("cvt.rna.tf32.f32 %0, %1;" : "=r"(u) : "f"(f));
    return __uint_as_float(u);
}

__device__ __forceinline__ void mma8(float* c, const float* a, const float* b) {
    asm volatile(
        "mma.sync.aligned.m16n8k8.row.col.f32.tf32.tf32.f32 "
        "{%0,%1,%2,%3}, {%4,%5,%6,%7}, {%8,%9}, {%0,%1,%2,%3};\n"
        : "+f"(c[0]), "+f"(c[1]), "+f"(c[2]), "+f"(c[3])
        : "r"(__float_as_uint(a[0])), "r"(__float_as_uint(a[1])),
          "r"(__float_as_uint(a[2])), "r"(__float_as_uint(a[3])),
          "r"(__float_as_uint(b[0])), "r"(__float_as_uint(b[1])));
}

__global__ void zero_cnt_kernel() {
    if (threadIdx.x < NEXP) g_cnt[threadIdx.x] = 0;
}

// ---------------- gating ----------------
__global__ __launch_bounds__(128) void gate_kernel(const float* __restrict__ x,
                                                   const float* __restrict__ Wg) {
    __shared__ float red[128 * NEXP];
    __shared__ float sc[NEXP];
    int t = blockIdx.x;
    const float* xr = x + (size_t)t * DIM_;
    float acc[NEXP];
#pragma unroll
    for (int e = 0; e < NEXP; e++) acc[e] = 0.f;
    for (int i = threadIdx.x; i < DIM_; i += 128) {
        float xv = xr[i];
        const float4* w4 = reinterpret_cast<const float4*>(Wg + (size_t)i * NEXP);
        float4 wa = w4[0], wb = w4[1];
        acc[0] += xv * wa.x; acc[1] += xv * wa.y;
        acc[2] += xv * wa.z; acc[3] += xv * wa.w;
        acc[4] += xv * wb.x; acc[5] += xv * wb.y;
        acc[6] += xv * wb.z; acc[7] += xv * wb.w;
    }
#pragma unroll
    for (int e = 0; e < NEXP; e++) red[threadIdx.x * NEXP + e] = acc[e];
    __syncthreads();
    if (threadIdx.x < NEXP) {
        int e = threadIdx.x;
        float s = 0.f;
        for (int i = 0; i < 128; i++) s += red[i * NEXP + e];
        sc[e] = s;
    }
    __syncthreads();
    if (threadIdx.x == 0) {
        int i1 = 0;
#pragma unroll
        for (int e = 1; e < NEXP; e++) if (sc[e] > sc[i1]) i1 = e;
        int i2 = (i1 == 0) ? 1 : 0;
#pragma unroll
        for (int e = 0; e < NEXP; e++) if (e != i1 && sc[e] > sc[i2]) i2 = e;
        float e2 = expf(sc[i2] - sc[i1]);
        float wa = 1.f / (1.f + e2);
        float wb = e2 / (1.f + e2);
        int s1 = atomicAdd(&g_cnt[i1], 1);
        g_tok[i1 * NTOK + s1] = t; g_wt[i1 * NTOK + s1] = wa;
        int s2 = atomicAdd(&g_cnt[i2], 1);
        g_tok[i2 * NTOK + s2] = t; g_wt[i2 * NTOK + s2] = wb;
    }
}

// ---------------- FFN1: gathered X @ {w1,w3} + SwiGLU -> g_act ----------------
// block 128x64x16, 8 warps (4x2), warp tile 32x32 doubled over {w1,w3}
__global__ __launch_bounds__(256) void ffn1_kernel(const float* __restrict__ x,
                                                   const float* __restrict__ w1,
                                                   const float* __restrict__ w3) {
    int e = blockIdx.z;
    int cnt = g_cnt[e];
    int m0 = blockIdx.x * BM;
    if (m0 >= cnt) return;
    int n0 = blockIdx.y * BN1;
    int base = 0;
#pragma unroll
    for (int i = 0; i < NEXP; i++) base += (i < e) ? g_cnt[i] : 0;

    const float* W1 = w1 + (size_t)e * DIM_ * HID_;
    const float* W3 = w3 + (size_t)e * DIM_ * HID_;

    __shared__ float As[BM][SA];
    __shared__ float B1s[BK][SB1];
    __shared__ float B3s[BK][SB1];
    __shared__ int   toks[BM];

    int tid = threadIdx.x;
    if (tid < BM) {
        int m = m0 + tid;
        toks[tid] = (m < cnt) ? g_tok[e * NTOK + m] : -1;
    }
    __syncthreads();

    int lane = tid & 31, warp = tid >> 5;
    int ar = tid >> 2, ac = (tid & 3) << 2;        // A rows ar, ar+64
    int t0 = toks[ar], t1 = toks[ar + 64];
    const float* xr0 = x + (size_t)(t0 < 0 ? 0 : t0) * DIM_;
    const float* xr1 = x + (size_t)(t1 < 0 ? 0 : t1) * DIM_;
    int br = tid >> 4, bc = (tid & 15) << 2;       // B: 16x64

    int wm = (warp >> 1) << 5;    // 0,32,64,96
    int wn = (warp & 1) << 5;     // 0,32
    int r = lane >> 2, q = lane & 3;

    float c1[2][4][4], c3[2][4][4];
#pragma unroll
    for (int i = 0; i < 2; i++)
#pragma unroll
        for (int j = 0; j < 4; j++)
#pragma unroll
            for (int k = 0; k < 4; k++) { c1[i][j][k] = 0.f; c3[i][j][k] = 0.f; }

    float4 a0v = make_float4(0.f,0.f,0.f,0.f), a1v = a0v, b1v, b3v;
    if (t0 >= 0) a0v = *reinterpret_cast<const float4*>(xr0 + ac);
    if (t1 >= 0) a1v = *reinterpret_cast<const float4*>(xr1 + ac);
    b1v = *reinterpret_cast<const float4*>(W1 + (size_t)br * HID_ + n0 + bc);
    b3v = *reinterpret_cast<const float4*>(W3 + (size_t)br * HID_ + n0 + bc);
    As[ar][ac+0]=to_tf32(a0v.x); As[ar][ac+1]=to_tf32(a0v.y);
    As[ar][ac+2]=to_tf32(a0v.z); As[ar][ac+3]=to_tf32(a0v.w);
    As[ar+64][ac+0]=to_tf32(a1v.x); As[ar+64][ac+1]=to_tf32(a1v.y);
    As[ar+64][ac+2]=to_tf32(a1v.z); As[ar+64][ac+3]=to_tf32(a1v.w);
    B1s[br][bc+0]=to_tf32(b1v.x); B1s[br][bc+1]=to_tf32(b1v.y);
    B1s[br][bc+2]=to_tf32(b1v.z); B1s[br][bc+3]=to_tf32(b1v.w);
    B3s[br][bc+0]=to_tf32(b3v.x); B3s[br][bc+1]=to_tf32(b3v.y);
    B3s[br][bc+2]=to_tf32(b3v.z); B3s[br][bc+3]=to_tf32(b3v.w);
    __syncthreads();

    for (int k0 = 0; k0 < DIM_; k0 += BK) {
        bool more = (k0 + BK) < DIM_;
        if (more) {
            int kn = k0 + BK;
            a0v = make_float4(0.f,0.f,0.f,0.f); a1v = a0v;
            if (t0 >= 0) a0v = *reinterpret_cast<const float4*>(xr0 + kn + ac);
            if (t1 >= 0) a1v = *reinterpret_cast<const float4*>(xr1 + kn + ac);
            b1v = *reinterpret_cast<const float4*>(W1 + (size_t)(kn + br) * HID_ + n0 + bc);
            b3v = *reinterpret_cast<const float4*>(W3 + (size_t)(kn + br) * HID_ + n0 + bc);
        }
#pragma unroll
        for (int ks = 0; ks < BK; ks += 8) {
            float a[2][4];
#pragma unroll
            for (int mi = 0; mi < 2; mi++) {
                int rb = wm + (mi << 4) + r;
                a[mi][0] = As[rb][ks + q];
                a[mi][1] = As[rb + 8][ks + q];
                a[mi][2] = As[rb][ks + q + 4];
                a[mi][3] = As[rb + 8][ks + q + 4];
            }
#pragma unroll
            for (int ni = 0; ni < 4; ni++) {
                int nb = wn + (ni << 3) + r;
                float b1f[2] = { B1s[ks + q][nb], B1s[ks + q + 4][nb] };
                float b3f[2] = { B3s[ks + q][nb], B3s[ks + q + 4][nb] };
#pragma unroll
                for (int mi = 0; mi < 2; mi++) {
                    mma8(c1[mi][ni], a[mi], b1f);
                    mma8(c3[mi][ni], a[mi], b3f);
                }
            }
        }
        __syncthreads();
        if (more) {
            As[ar][ac+0]=to_tf32(a0v.x); As[ar][ac+1]=to_tf32(a0v.y);
            As[ar][ac+2]=to_tf32(a0v.z); As[ar][ac+3]=to_tf32(a0v.w);
            As[ar+64][ac+0]=to_tf32(a1v.x); As[ar+64][ac+1]=to_tf32(a1v.y);
            As[ar+64][ac+2]=to_tf32(a1v.z); As[ar+64][ac+3]=to_tf32(a1v.w);
            B1s[br][bc+0]=to_tf32(b1v.x); B1s[br][bc+1]=to_tf32(b1v.y);
            B1s[br][bc+2]=to_tf32(b1v.z); B1s[br][bc+3]=to_tf32(b1v.w);
            B3s[br][bc+0]=to_tf32(b3v.x); B3s[br][bc+1]=to_tf32(b3v.y);
            B3s[br][bc+2]=to_tf32(b3v.z); B3s[br][bc+3]=to_tf32(b3v.w);
            __syncthreads();
        }
    }
    // epilogue: SwiGLU -> activation scratch
#pragma unroll
    for (int mi = 0; mi < 2; mi++) {
#pragma unroll
        for (int rr = 0; rr < 2; rr++) {
            int m = m0 + wm + (mi << 4) + r + (rr << 3);
            if (m < cnt) {
                size_t rowoff = (size_t)(base + m) * HID_;
#pragma unroll
                for (int ni = 0; ni < 4; ni++) {
                    int col = n0 + wn + (ni << 3) + (q << 1);
                    float u0 = c1[mi][ni][(rr << 1)],     v0 = c3[mi][ni][(rr << 1)];
                    float u1 = c1[mi][ni][(rr << 1) + 1], v1 = c3[mi][ni][(rr << 1) + 1];
                    float2 h;
                    h.x = (u0 / (1.f + expf(-u0))) * v0;
                    h.y = (u1 / (1.f + expf(-u1))) * v1;
                    *reinterpret_cast<float2*>(&g_act[rowoff + col]) = h;
                }
            }
        }
    }
}

// ---------------- FFN2: g_act @ w2 -> weighted scatter-add ----------------
// block 128x128x16, 8 warps (4x2), warp tile 32x64
__global__ __launch_bounds__(256) void ffn2_kernel(const float* __restrict__ w2,
                                                   float* __restrict__ out) {
    int e = blockIdx.z;
    int cnt = g_cnt[e];
    int m0 = blockIdx.x * BM;
    if (m0 >= cnt) return;
    int n0 = blockIdx.y * BN2;
    int base = 0;
#pragma unroll
    for (int i = 0; i < NEXP; i++) base += (i < e) ? g_cnt[i] : 0;
    const float* W2 = w2 + (size_t)e * HID_ * DIM_;

    __shared__ float As[BM][SA];
    __shared__ float Bs[BK][SB2];

    int tid = threadIdx.x;
    int lane = tid & 31, warp = tid >> 5;
    int ar = tid >> 2, ac = (tid & 3) << 2;       // A rows ar, ar+64
    bool v0 = (m0 + ar) < cnt, v1 = (m0 + ar + 64) < cnt;
    const float* ar0 = g_act + (size_t)(base + m0 + (v0 ? ar : 0)) * HID_;
    const float* ar1 = g_act + (size_t)(base + m0 + (v1 ? ar + 64 : 0)) * HID_;
    int br = tid >> 5, bc = (tid & 31) << 2;      // B rows br, br+8; 16x128

    int wm = (warp >> 1) << 5;   // 0,32,64,96
    int wn = (warp & 1) << 6;    // 0,64
    int r = lane >> 2, q = lane & 3;

    float c[2][8][4];
#pragma unroll
    for (int i = 0; i < 2; i++)
#pragma unroll
        for (int j = 0; j < 8; j++)
#pragma unroll
            for (int k = 0; k < 4; k++) c[i][j][k] = 0.f;

    float4 a0v = make_float4(0.f,0.f,0.f,0.f), a1v = a0v, b0v, b1v;
    if (v0) a0v = *reinterpret_cast<const float4*>(ar0 + ac);
    if (v1) a1v = *reinterpret_cast<const float4*>(ar1 + ac);
    b0v = *reinterpret_cast<const float4*>(W2 + (size_t)br * DIM_ + n0 + bc);
    b1v = *reinterpret_cast<const float4*>(W2 + (size_t)(br + 8) * DIM_ + n0 + bc);
    As[ar][ac+0]=to_tf32(a0v.x); As[ar][ac+1]=to_tf32(a0v.y);
    As[ar][ac+2]=to_tf32(a0v.z); As[ar][ac+3]=to_tf32(a0v.w);
    As[ar+64][ac+0]=to_tf32(a1v.x); As[ar+64][ac+1]=to_tf32(a1v.y);
    As[ar+64][ac+2]=to_tf32(a1v.z); As[ar+64][ac+3]=to_tf32(a1v.w);
    Bs[br][bc+0]=to_tf32(b0v.x); Bs[br][bc+1]=to_tf32(b0v.y);
    Bs[br][bc+2]=to_tf32(b0v.z); Bs[br][bc+3]=to_tf32(b0v.w);
    Bs[br+8][bc+0]=to_tf32(b1v.x); Bs[br+8][bc+1]=to_tf32(b1v.y);
    Bs[br+8][bc+2]=to_tf32(b1v.z); Bs[br+8][bc+3]=to_tf32(b1v.w);
    __syncthreads();

    for (int k0 = 0; k0 < HID_; k0 += BK) {
        bool more = (k0 + BK) < HID_;
        if (more) {
            int kn = k0 + BK;
            a0v = make_float4(0.f,0.f,0.f,0.f); a1v = a0v;
            if (v0) a0v = *reinterpret_cast<const float4*>(ar0 + kn + ac);
            if (v1) a1v = *reinterpret_cast<const float4*>(ar1 + kn + ac);
            b0v = *reinterpret_cast<const float4*>(W2 + (size_t)(kn + br) * DIM_ + n0 + bc);
            b1v = *reinterpret_cast<const float4*>(W2 + (size_t)(kn + br + 8) * DIM_ + n0 + bc);
        }
#pragma unroll
        for (int ks = 0; ks < BK; ks += 8) {
            float a[2][4];
#pragma unroll
            for (int mi = 0; mi < 2; mi++) {
                int rb = wm + (mi << 4) + r;
                a[mi][0] = As[rb][ks + q];
                a[mi][1] = As[rb + 8][ks + q];
                a[mi][2] = As[rb][ks + q + 4];
                a[mi][3] = As[rb + 8][ks + q + 4];
            }
            float b[8][2];
#pragma unroll
            for (int ni = 0; ni < 8; ni++) {
                int nb = wn + (ni << 3) + r;
                b[ni][0] = Bs[ks + q][nb];
                b[ni][1] = Bs[ks + q + 4][nb];
            }
#pragma unroll
            for (int ni = 0; ni < 8; ni++)
#pragma unroll
                for (int mi = 0; mi < 2; mi++)
                    mma8(c[mi][ni], a[mi], b[ni]);
        }
        __syncthreads();
        if (more) {
            As[ar][ac+0]=to_tf32(a0v.x); As[ar][ac+1]=to_tf32(a0v.y);
            As[ar][ac+2]=to_tf32(a0v.z); As[ar][ac+3]=to_tf32(a0v.w);
            As[ar+64][ac+0]=to_tf32(a1v.x); As[ar+64][ac+1]=to_tf32(a1v.y);
            As[ar+64][ac+2]=to_tf32(a1v.z); As[ar+64][ac+3]=to_tf32(a1v.w);
            Bs[br][bc+0]=to_tf32(b0v.x); Bs[br][bc+1]=to_tf32(b0v.y);
            Bs[br][bc+2]=to_tf32(b0v.z); Bs[br][bc+3]=to_tf32(b0v.w);
            Bs[br+8][bc+0]=to_tf32(b1v.x); Bs[br+8][bc+1]=to_tf32(b1v.y);
            Bs[br+8][bc+2]=to_tf32(b1v.z); Bs[br+8][bc+3]=to_tf32(b1v.w);
            __syncthreads();
        }
    }
    // epilogue: weighted scatter-add
#pragma unroll
    for (int mi = 0; mi < 2; mi++) {
#pragma unroll
        for (int rr = 0; rr < 2; rr++) {
            int m = m0 + wm + (mi << 4) + r + (rr << 3);
            if (m < cnt) {
                int t = g_tok[e * NTOK + m];
                float wgt = g_wt[e * NTOK + m];
                float* orow = out + (size_t)t * DIM_;
#pragma unroll
                for (int ni = 0; ni < 8; ni++) {
                    int col = n0 + wn + (ni << 3) + (q << 1);
                    atomicAdd(&orow[col],     wgt * c[mi][ni][(rr << 1)]);
                    atomicAdd(&orow[col + 1], wgt * c[mi][ni][(rr << 1) + 1]);
                }
            }
        }
    }
}

// ---------------- launch ----------------
extern "C" void kernel_launch(void* const* d_in, const int* in_sizes, int n_in,
                              void* d_out, int out_size) {
    const float* x  = (const float*)d_in[0];
    const float* Wg = (const float*)d_in[1];
    const float* w1 = (const float*)d_in[2];
    const float* w3 = (const float*)d_in[3];
    const float* w2 = (const float*)d_in[4];
    float* out = (float*)d_out;

    cudaMemsetAsync(out, 0, (size_t)out_size * sizeof(float), 0);
    zero_cnt_kernel<<<1, 32>>>();
    gate_kernel<<<NTOK, 128>>>(x, Wg);
    dim3 g1(NTOK / BM, HID_ / BN1, NEXP);
    ffn1_kernel<<<g1, 256>>>(x, w1, w3);
    dim3 g2(NTOK / BM, DIM_ / BN2, NEXP);
    ffn2_kernel<<<g2, 256>>>(w2, out);
}

// round 5
// speedup vs baseline: 1.3311x; 1.1170x over previous
#include <cuda_runtime.h>
#include <math.h>

#define NTOK 2048
#define DIM_ 2048
#define HID_ 7168
#define NEXP 8

#define BM  128
#define BK  32
#define BN1 64      // ffn1 N tile (doubled over w1/w3 -> 128 effective)
#define BN2 128     // ffn2 N tile
#define SA  36      // A stride: 36 mod 32 = 4 -> 4r+q conflict-free
#define SB1 72      // 72 mod 32 = 8 -> 8q+r conflict-free
#define SB2 136     // 136 mod 32 = 8 -> conflict-free

#define F1_SMEM ((2*BM*SA + 2*2*BK*SB1) * 4)   // 73728 B
#define F2_SMEM ((2*BM*SA + 2*BK*SB2) * 4)     // 71680 B

// ---------------- device scratch ----------------
__device__ int   g_cnt[NEXP];
__device__ int   g_tok[NEXP * NTOK];
__device__ float g_wt [NEXP * NTOK];
__device__ float g_act[(size_t)NTOK * 2 * HID_];

// ---------------- helpers ----------------
__device__ __forceinline__ float to_tf32(float f) {
    unsigned u;
    asm("cvt.rna.tf32.f32 %0, %1;" : "=r"(u) : "f"(f));
    return __uint_as_float(u);
}

__device__ __forceinline__ void mma8(float* c, const float* a, const float* b) {
    asm volatile(
        "mma.sync.aligned.m16n8k8.row.col.f32.tf32.tf32.f32 "
        "{%0,%1,%2,%3}, {%4,%5,%6,%7}, {%8,%9}, {%0,%1,%2,%3};\n"
        : "+f"(c[0]), "+f"(c[1]), "+f"(c[2]), "+f"(c[3])
        : "r"(__float_as_uint(a[0])), "r"(__float_as_uint(a[1])),
          "r"(__float_as_uint(a[2])), "r"(__float_as_uint(a[3])),
          "r"(__float_as_uint(b[0])), "r"(__float_as_uint(b[1])));
}

__device__ __forceinline__ void st4(float* p, float4 v) {
    p[0] = to_tf32(v.x); p[1] = to_tf32(v.y);
    p[2] = to_tf32(v.z); p[3] = to_tf32(v.w);
}

__global__ void zero_cnt_kernel() {
    if (threadIdx.x < NEXP) g_cnt[threadIdx.x] = 0;
}

// ---------------- gating ----------------
__global__ __launch_bounds__(128) void gate_kernel(const float* __restrict__ x,
                                                   const float* __restrict__ Wg) {
    __shared__ float red[128 * NEXP];
    __shared__ float sc[NEXP];
    int t = blockIdx.x;
    const float* xr = x + (size_t)t * DIM_;
    float acc[NEXP];
#pragma unroll
    for (int e = 0; e < NEXP; e++) acc[e] = 0.f;
    for (int i = threadIdx.x; i < DIM_; i += 128) {
        float xv = xr[i];
        const float4* w4 = reinterpret_cast<const float4*>(Wg + (size_t)i * NEXP);
        float4 wa = w4[0], wb = w4[1];
        acc[0] += xv * wa.x; acc[1] += xv * wa.y;
        acc[2] += xv * wa.z; acc[3] += xv * wa.w;
        acc[4] += xv * wb.x; acc[5] += xv * wb.y;
        acc[6] += xv * wb.z; acc[7] += xv * wb.w;
    }
#pragma unroll
    for (int e = 0; e < NEXP; e++) red[threadIdx.x * NEXP + e] = acc[e];
    __syncthreads();
    if (threadIdx.x < NEXP) {
        int e = threadIdx.x;
        float s = 0.f;
        for (int i = 0; i < 128; i++) s += red[i * NEXP + e];
        sc[e] = s;
    }
    __syncthreads();
    if (threadIdx.x == 0) {
        int i1 = 0;
#pragma unroll
        for (int e = 1; e < NEXP; e++) if (sc[e] > sc[i1]) i1 = e;
        int i2 = (i1 == 0) ? 1 : 0;
#pragma unroll
        for (int e = 0; e < NEXP; e++) if (e != i1 && sc[e] > sc[i2]) i2 = e;
        float e2 = expf(sc[i2] - sc[i1]);
        float wa = 1.f / (1.f + e2);
        float wb = e2 / (1.f + e2);
        int s1 = atomicAdd(&g_cnt[i1], 1);
        g_tok[i1 * NTOK + s1] = t; g_wt[i1 * NTOK + s1] = wa;
        int s2 = atomicAdd(&g_cnt[i2], 1);
        g_tok[i2 * NTOK + s2] = t; g_wt[i2 * NTOK + s2] = wb;
    }
}

// ---------------- FFN1: gathered X @ {w1,w3} + SwiGLU -> g_act ----------------
__global__ __launch_bounds__(256, 2) void ffn1_kernel(const float* __restrict__ x,
                                                      const float* __restrict__ w1,
                                                      const float* __restrict__ w3) {
    extern __shared__ float sm[];
    float (*As)[BM][SA]  = reinterpret_cast<float(*)[BM][SA]>(sm);
    float (*B1s)[BK][SB1] = reinterpret_cast<float(*)[BK][SB1]>(sm + 2 * BM * SA);
    float (*B3s)[BK][SB1] = reinterpret_cast<float(*)[BK][SB1]>(sm + 2 * BM * SA + 2 * BK * SB1);
    __shared__ int toks[BM];

    int e = blockIdx.z;
    int cnt = g_cnt[e];
    int m0 = blockIdx.x * BM;
    if (m0 >= cnt) return;
    int n0 = blockIdx.y * BN1;
    int base = 0;
#pragma unroll
    for (int i = 0; i < NEXP; i++) base += (i < e) ? g_cnt[i] : 0;
    const float* W1 = w1 + (size_t)e * DIM_ * HID_;
    const float* W3 = w3 + (size_t)e * DIM_ * HID_;

    int tid = threadIdx.x;
    if (tid < BM) {
        int m = m0 + tid;
        toks[tid] = (m < cnt) ? g_tok[e * NTOK + m] : -1;
    }
    __syncthreads();

    int lane = tid & 31, warp = tid >> 5;
    // A loader: rows (tid>>2) and +64, cols (tid&3)*8 .. +7
    int lar = tid >> 2, lac = (tid & 3) << 3;
    int lt0 = toks[lar], lt1 = toks[lar + 64];
    const float* xr0 = x + (size_t)(lt0 < 0 ? 0 : lt0) * DIM_;
    const float* xr1 = x + (size_t)(lt1 < 0 ? 0 : lt1) * DIM_;
    // B loader: rows (tid>>4) and +16, cols (tid&15)*4
    int lbr = tid >> 4, lbc = (tid & 15) << 2;

    int wm = (warp >> 1) << 5;    // 0,32,64,96
    int wn = (warp & 1) << 5;     // 0,32
    int r = lane >> 2, q = lane & 3;

    float c1[2][4][4], c3[2][4][4];
#pragma unroll
    for (int i = 0; i < 2; i++)
#pragma unroll
        for (int j = 0; j < 4; j++)
#pragma unroll
            for (int k = 0; k < 4; k++) { c1[i][j][k] = 0.f; c3[i][j][k] = 0.f; }

#define F1_STAGE(K0, BUF) do {                                                     \
    float4 z = make_float4(0.f, 0.f, 0.f, 0.f);                                    \
    float4 a00 = z, a01 = z, a10 = z, a11 = z;                                     \
    if (lt0 >= 0) { a00 = *reinterpret_cast<const float4*>(xr0 + (K0) + lac);      \
                    a01 = *reinterpret_cast<const float4*>(xr0 + (K0) + lac + 4); }\
    if (lt1 >= 0) { a10 = *reinterpret_cast<const float4*>(xr1 + (K0) + lac);      \
                    a11 = *reinterpret_cast<const float4*>(xr1 + (K0) + lac + 4); }\
    size_t o0 = (size_t)((K0) + lbr) * HID_ + n0 + lbc;                            \
    size_t o1 = (size_t)((K0) + lbr + 16) * HID_ + n0 + lbc;                       \
    float4 b10 = *reinterpret_cast<const float4*>(W1 + o0);                        \
    float4 b11 = *reinterpret_cast<const float4*>(W1 + o1);                        \
    float4 b30 = *reinterpret_cast<const float4*>(W3 + o0);                        \
    float4 b31 = *reinterpret_cast<const float4*>(W3 + o1);                        \
    st4(&As[BUF][lar][lac], a00);      st4(&As[BUF][lar][lac + 4], a01);           \
    st4(&As[BUF][lar + 64][lac], a10); st4(&As[BUF][lar + 64][lac + 4], a11);      \
    st4(&B1s[BUF][lbr][lbc], b10);     st4(&B1s[BUF][lbr + 16][lbc], b11);         \
    st4(&B3s[BUF][lbr][lbc], b30);     st4(&B3s[BUF][lbr + 16][lbc], b31);         \
} while (0)

    F1_STAGE(0, 0);
    __syncthreads();

    const int NT = DIM_ / BK;
    for (int t = 0; t < NT; t++) {
        int cur = t & 1;
        if (t + 1 < NT) F1_STAGE((t + 1) * BK, cur ^ 1);
#pragma unroll
        for (int ks = 0; ks < BK; ks += 8) {
            float a[2][4];
#pragma unroll
            for (int mi = 0; mi < 2; mi++) {
                int rb = wm + (mi << 4) + r;
                a[mi][0] = As[cur][rb][ks + q];
                a[mi][1] = As[cur][rb + 8][ks + q];
                a[mi][2] = As[cur][rb][ks + q + 4];
                a[mi][3] = As[cur][rb + 8][ks + q + 4];
            }
#pragma unroll
            for (int ni = 0; ni < 4; ni++) {
                int nb = wn + (ni << 3) + r;
                float b1f[2] = { B1s[cur][ks + q][nb], B1s[cur][ks + q + 4][nb] };
                float b3f[2] = { B3s[cur][ks + q][nb], B3s[cur][ks + q + 4][nb] };
#pragma unroll
                for (int mi = 0; mi < 2; mi++) {
                    mma8(c1[mi][ni], a[mi], b1f);
                    mma8(c3[mi][ni], a[mi], b3f);
                }
            }
        }
        __syncthreads();
    }

    // epilogue: SwiGLU -> g_act
#pragma unroll
    for (int mi = 0; mi < 2; mi++) {
#pragma unroll
        for (int rr = 0; rr < 2; rr++) {
            int m = m0 + wm + (mi << 4) + r + (rr << 3);
            if (m < cnt) {
                size_t rowoff = (size_t)(base + m) * HID_;
#pragma unroll
                for (int ni = 0; ni < 4; ni++) {
                    int col = n0 + wn + (ni << 3) + (q << 1);
                    float u0 = c1[mi][ni][(rr << 1)],     v0 = c3[mi][ni][(rr << 1)];
                    float u1 = c1[mi][ni][(rr << 1) + 1], v1 = c3[mi][ni][(rr << 1) + 1];
                    float2 h;
                    h.x = (u0 / (1.f + expf(-u0))) * v0;
                    h.y = (u1 / (1.f + expf(-u1))) * v1;
                    *reinterpret_cast<float2*>(&g_act[rowoff + col]) = h;
                }
            }
        }
    }
}

// ---------------- FFN2: g_act @ w2 -> weighted scatter-add ----------------
__global__ __launch_bounds__(256, 2) void ffn2_kernel(const float* __restrict__ w2,
                                                      float* __restrict__ out) {
    extern __shared__ float sm[];
    float (*As)[BM][SA] = reinterpret_cast<float(*)[BM][SA]>(sm);
    float (*Bs)[BK][SB2] = reinterpret_cast<float(*)[BK][SB2]>(sm + 2 * BM * SA);

    int e = blockIdx.z;
    int cnt = g_cnt[e];
    int m0 = blockIdx.x * BM;
    if (m0 >= cnt) return;
    int n0 = blockIdx.y * BN2;
    int base = 0;
#pragma unroll
    for (int i = 0; i < NEXP; i++) base += (i < e) ? g_cnt[i] : 0;
    const float* W2 = w2 + (size_t)e * HID_ * DIM_;

    int tid = threadIdx.x;
    int lane = tid & 31, warp = tid >> 5;
    // A loader: rows (tid>>2), +64; cols (tid&3)*8
    int lar = tid >> 2, lac = (tid & 3) << 3;
    bool v0 = (m0 + lar) < cnt, v1 = (m0 + lar + 64) < cnt;
    const float* ar0 = g_act + (size_t)(base + m0 + (v0 ? lar : 0)) * HID_;
    const float* ar1 = g_act + (size_t)(base + m0 + (v1 ? lar + 64 : 0)) * HID_;
    // B loader: rows (tid>>5) + 8h (h=0..3); cols (tid&31)*4
    int lbr = tid >> 5, lbc = (tid & 31) << 2;

    int wm = (warp >> 1) << 5;   // 0,32,64,96
    int wn = (warp & 1) << 6;    // 0,64
    int r = lane >> 2, q = lane & 3;

    float c[2][8][4];
#pragma unroll
    for (int i = 0; i < 2; i++)
#pragma unroll
        for (int j = 0; j < 8; j++)
#pragma unroll
            for (int k = 0; k < 4; k++) c[i][j][k] = 0.f;

#define F2_STAGE(K0, BUF) do {                                                     \
    float4 z = make_float4(0.f, 0.f, 0.f, 0.f);                                    \
    float4 a00 = z, a01 = z, a10 = z, a11 = z;                                     \
    if (v0) { a00 = *reinterpret_cast<const float4*>(ar0 + (K0) + lac);            \
              a01 = *reinterpret_cast<const float4*>(ar0 + (K0) + lac + 4); }      \
    if (v1) { a10 = *reinterpret_cast<const float4*>(ar1 + (K0) + lac);            \
              a11 = *reinterpret_cast<const float4*>(ar1 + (K0) + lac + 4); }      \
    float4 bv0 = *reinterpret_cast<const float4*>(W2 + (size_t)((K0) + lbr) * DIM_ + n0 + lbc);      \
    float4 bv1 = *reinterpret_cast<const float4*>(W2 + (size_t)((K0) + lbr + 8) * DIM_ + n0 + lbc);  \
    float4 bv2 = *reinterpret_cast<const float4*>(W2 + (size_t)((K0) + lbr + 16) * DIM_ + n0 + lbc); \
    float4 bv3 = *reinterpret_cast<const float4*>(W2 + (size_t)((K0) + lbr + 24) * DIM_ + n0 + lbc); \
    st4(&As[BUF][lar][lac], a00);      st4(&As[BUF][lar][lac + 4], a01);           \
    st4(&As[BUF][lar + 64][lac], a10); st4(&As[BUF][lar + 64][lac + 4], a11);      \
    st4(&Bs[BUF][lbr][lbc], bv0);      st4(&Bs[BUF][lbr + 8][lbc], bv1);           \
    st4(&Bs[BUF][lbr + 16][lbc], bv2); st4(&Bs[BUF][lbr + 24][lbc], bv3);          \
} while (0)

    F2_STAGE(0, 0);
    __syncthreads();

    const int NT = HID_ / BK;
    for (int t = 0; t < NT; t++) {
        int cur = t & 1;
        if (t + 1 < NT) F2_STAGE((t + 1) * BK, cur ^ 1);
#pragma unroll
        for (int ks = 0; ks < BK; ks += 8) {
            float a[2][4];
#pragma unroll
            for (int mi = 0; mi < 2; mi++) {
                int rb = wm + (mi << 4) + r;
                a[mi][0] = As[cur][rb][ks + q];
                a[mi][1] = As[cur][rb + 8][ks + q];
                a[mi][2] = As[cur][rb][ks + q + 4];
                a[mi][3] = As[cur][rb + 8][ks + q + 4];
            }
            float b[8][2];
#pragma unroll
            for (int ni = 0; ni < 8; ni++) {
                int nb = wn + (ni << 3) + r;
                b[ni][0] = Bs[cur][ks + q][nb];
                b[ni][1] = Bs[cur][ks + q + 4][nb];
            }
#pragma unroll
            for (int ni = 0; ni < 8; ni++)
#pragma unroll
                for (int mi = 0; mi < 2; mi++)
                    mma8(c[mi][ni], a[mi], b[ni]);
        }
        __syncthreads();
    }

    // epilogue: weighted scatter-add
#pragma unroll
    for (int mi = 0; mi < 2; mi++) {
#pragma unroll
        for (int rr = 0; rr < 2; rr++) {
            int m = m0 + wm + (mi << 4) + r + (rr << 3);
            if (m < cnt) {
                int t = g_tok[e * NTOK + m];
                float wgt = g_wt[e * NTOK + m];
                float* orow = out + (size_t)t * DIM_;
#pragma unroll
                for (int ni = 0; ni < 8; ni++) {
                    int col = n0 + wn + (ni << 3) + (q << 1);
                    atomicAdd(&orow[col],     wgt * c[mi][ni][(rr << 1)]);
                    atomicAdd(&orow[col + 1], wgt * c[mi][ni][(rr << 1) + 1]);
                }
            }
        }
    }
}

// ---------------- launch ----------------
extern "C" void kernel_launch(void* const* d_in, const int* in_sizes, int n_in,
                              void* d_out, int out_size) {
    const float* x  = (const float*)d_in[0];
    const float* Wg = (const float*)d_in[1];
    const float* w1 = (const float*)d_in[2];
    const float* w3 = (const float*)d_in[3];
    const float* w2 = (const float*)d_in[4];
    float* out = (float*)d_out;
    (void)in_sizes; (void)n_in;

    static int attr_done = 0;
    if (!attr_done) {
        cudaFuncSetAttribute(ffn1_kernel, cudaFuncAttributeMaxDynamicSharedMemorySize, F1_SMEM);
        cudaFuncSetAttribute(ffn2_kernel, cudaFuncAttributeMaxDynamicSharedMemorySize, F2_SMEM);
        attr_done = 1;
    }

    cudaMemsetAsync(out, 0, (size_t)out_size * sizeof(float), 0);
    zero_cnt_kernel<<<1, 32>>>();
    gate_kernel<<<NTOK, 128>>>(x, Wg);
    ffn1_kernel<<<dim3(NTOK / BM, HID_ / BN1, NEXP), 256, F1_SMEM>>>(x, w1, w3);
    ffn2_kernel<<<dim3(NTOK / BM, DIM_ / BN2, NEXP), 256, F2_SMEM>>>(w2, out);
}